// round 5
// baseline (speedup 1.0000x reference)
#include <cuda_runtime.h>
#include <cuda.h>
#include <cuda_fp16.h>
#include <cstdint>

// ===================== problem dims =====================
static constexpr int T_TOK = 8192;   // tokens (M)
static constexpr int K_DIM = 4096;   // input size (K)
static constexpr int O_DIM = 6144;   // output size (N)
static constexpr float FP8_MAX = 448.0f;

// ===================== scratch (device globals; no allocation allowed) =====================
__device__ __align__(1024) uint8_t g_xq[(size_t)T_TOK * K_DIM];   // 32 MB: e4m3(x/xs)
__device__ __align__(1024) uint8_t g_wq[(size_t)O_DIM * K_DIM];   // 24 MB: e4m3(w)
__device__ float g_xs[T_TOK];

// ===================== PTX helpers =====================
__device__ __forceinline__ uint32_t smem_u32(const void* p) {
    uint32_t a;
    asm("{ .reg .u64 t; cvta.to.shared.u64 t, %1; cvt.u32.u64 %0, t; }" : "=r"(a) : "l"(p));
    return a;
}

#define MBAR_INIT(addr, cnt) \
    asm volatile("mbarrier.init.shared.b64 [%0], %1;" :: "r"(addr), "r"(cnt) : "memory")
#define MBAR_EXPECT_TX(addr, bytes) \
    asm volatile("mbarrier.arrive.expect_tx.shared.b64 _, [%0], %1;" :: "r"(addr), "r"(bytes) : "memory")
#define MBAR_ARRIVE(addr) \
    asm volatile("mbarrier.arrive.shared.b64 _, [%0];" :: "r"(addr) : "memory")

#define MBAR_WAIT(addr, ph) do {                                                   \
    asm volatile("{\n\t.reg .pred P;\n\tWL%=:\n\t"                                 \
        "mbarrier.try_wait.parity.acquire.cta.shared::cta.b64 P, [%0], %1, 0x989680;\n\t" \
        "@P bra.uni WD%=;\n\tbra.uni WL%=;\n\tWD%=:\n\t}"                          \
        :: "r"(addr), "r"(ph) : "memory");                                         \
} while (0)

#define TMA_LOAD_3D(dst, map, cx, cy, cz, mbar) \
    asm volatile("cp.async.bulk.tensor.3d.shared::cta.global.tile.mbarrier::complete_tx::bytes " \
                 "[%0], [%1, {%2, %3, %4}], [%5];" \
                 :: "r"((uint32_t)(dst)), "l"(map), "r"((int32_t)(cx)), "r"((int32_t)(cy)), \
                    "r"((int32_t)(cz)), "r"((uint32_t)(mbar)) : "memory")

#define LDSM_X4(r0, r1, r2, r3, addr) \
    asm volatile("ldmatrix.sync.aligned.m8n8.x4.shared.b16 {%0,%1,%2,%3}, [%4];" \
                 : "=r"(r0), "=r"(r1), "=r"(r2), "=r"(r3) : "r"(addr))

// fp16 x fp16 -> f32 mma (the fast path on this toolchain)
#define HMMA16816(c, a0, a1, a2, a3, b0v, b1v) \
    asm volatile("mma.sync.aligned.m16n8k16.row.col.f32.f16.f16.f32 " \
                 "{%0,%1,%2,%3},{%4,%5,%6,%7},{%8,%9},{%0,%1,%2,%3};" \
                 : "+f"((c)[0]), "+f"((c)[1]), "+f"((c)[2]), "+f"((c)[3]) \
                 : "r"(a0), "r"(a1), "r"(a2), "r"(a3), "r"(b0v), "r"(b1v))

__device__ __forceinline__ uint32_t swz128(uint32_t base, uint32_t off) {
    return base + (off ^ ((off >> 3) & 0x70));
}

// expand packed e4m3 pairs -> f16x2 (exact)
__device__ __forceinline__ uint32_t cvt_lo(uint32_t r) {
    unsigned short h = (unsigned short)(r & 0xFFFFu);
    uint32_t d;
    asm("cvt.rn.f16x2.e4m3x2 %0, %1;" : "=r"(d) : "h"(h));
    return d;
}
__device__ __forceinline__ uint32_t cvt_hi(uint32_t r) {
    unsigned short h = (unsigned short)(r >> 16);
    uint32_t d;
    asm("cvt.rn.f16x2.e4m3x2 %0, %1;" : "=r"(d) : "h"(h));
    return d;
}
__device__ __forceinline__ uint32_t hmul2u(uint32_t a, uint32_t s) {
    uint32_t d;
    asm("mul.rn.f16x2 %0, %1, %2;" : "=r"(d) : "r"(a), "r"(s));
    return d;
}

// f32 pair -> packed e4m3x2 (byte0 = lo)
__device__ __forceinline__ uint32_t pack_e4m3_2(float lo, float hi) {
    unsigned short p;
    asm volatile("cvt.rn.satfinite.e4m3x2.f32 %0, %1, %2;" : "=h"(p) : "f"(hi), "f"(lo));
    return (uint32_t)p;
}
__device__ __forceinline__ uint32_t pack_e4m3_4(float a, float b, float c, float d) {
    return pack_e4m3_2(a, b) | (pack_e4m3_2(c, d) << 16);
}

// ===================== kernel 1: per-token quantize x -> e4m3 =====================
__global__ void __launch_bounds__(256) quant_x_kernel(const float* __restrict__ x) {
    int row = blockIdx.x;
    int t = threadIdx.x;
    const float4* xr = reinterpret_cast<const float4*>(x + (size_t)row * K_DIM);
    float4 v[4];
    float amax = 0.f;
#pragma unroll
    for (int j = 0; j < 4; ++j) {
        v[j] = xr[t + 256 * j];
        amax = fmaxf(amax, fabsf(v[j].x));
        amax = fmaxf(amax, fabsf(v[j].y));
        amax = fmaxf(amax, fabsf(v[j].z));
        amax = fmaxf(amax, fabsf(v[j].w));
    }
#pragma unroll
    for (int off = 16; off > 0; off >>= 1)
        amax = fmaxf(amax, __shfl_xor_sync(0xFFFFFFFFu, amax, off));
    __shared__ float smax[8];
    if ((t & 31) == 0) smax[t >> 5] = amax;
    __syncthreads();
    float rmax = smax[0];
#pragma unroll
    for (int j = 1; j < 8; ++j) rmax = fmaxf(rmax, smax[j]);
    float scale = fmaxf(rmax, 1e-12f) / FP8_MAX;
    if (t == 0) g_xs[row] = scale;
    uint32_t* outr = reinterpret_cast<uint32_t*>(g_xq + (size_t)row * K_DIM);
#pragma unroll
    for (int j = 0; j < 4; ++j) {
        outr[t + 256 * j] = pack_e4m3_4(v[j].x / scale, v[j].y / scale,
                                        v[j].z / scale, v[j].w / scale);
    }
}

// ===================== kernel 2: quantize weights -> e4m3 (raw, no scale) =====================
__global__ void __launch_bounds__(256) quant_w_kernel(const float* __restrict__ w) {
    int idx4 = blockIdx.x * 256 + threadIdx.x;   // float4 index
    float4 v = reinterpret_cast<const float4*>(w)[idx4];
    reinterpret_cast<uint32_t*>(g_wq)[idx4] = pack_e4m3_4(v.x, v.y, v.z, v.w);
}

// ===================== kernel 3: GEMM — fp8 in SMEM, f16 HMMA in registers =====================
static constexpr int STAGES   = 4;
static constexpr int KCHUNK   = 128;              // fp8 elems per stage (=128B row, = 1 scale block)
static constexpr int K_ITERS  = K_DIM / KCHUNK;   // 32
static constexpr int CTA_M    = 128;
static constexpr int CTA_N    = 256;
static constexpr int A_STG_B  = CTA_M * 128;      // 16 KB
static constexpr int B_STG_B  = CTA_N * 128;      // 32 KB
static constexpr int SMEM_BYTES = 1024 + STAGES * (A_STG_B + B_STG_B);  // 197632

#define BAR_FULL(s)  (smem_base + 0  + (s) * 8)
#define BAR_EMPTY(s) (smem_base + 64 + (s) * 8)
#define SCALE_SM     (smem_base + 256)            // 64 floats (2 o-blocks x 32 k-blocks)
#define A_STAGE(s)   (smem_base + 1024 + (s) * (A_STG_B + B_STG_B))
#define B_STAGE(s)   (A_STAGE(s) + A_STG_B)

__global__ void __launch_bounds__(288, 1)
gemm_kernel(const __grid_constant__ CUtensorMap tma_a,
            const __grid_constant__ CUtensorMap tma_b,
            const float* __restrict__ wsi,
            float* __restrict__ out) {
    extern __shared__ char smem[];
    const uint32_t smem_base = smem_u32(smem);
    const int tid = threadIdx.x;
    const int wid = tid >> 5;
    const int lane = tid & 31;

    const int m_tile = blockIdx.x & 63;          // m fastest: concurrent CTAs share B in L2
    const int n_tile = blockIdx.x >> 6;          // 24 N tiles
    const int m_cta = m_tile * CTA_M;
    const int n_cta = n_tile * CTA_N;

    if (tid == 0) {
        for (int s = 0; s < STAGES; ++s) {
            MBAR_INIT(BAR_FULL(s), 1);
            MBAR_INIT(BAR_EMPTY(s), 8);   // 8 consumer warps
        }
    }
    // weight scales for this CTA: 2 o-blocks x 32 k-blocks
    if (tid < 64) {
        int ob = tid >> 5;     // local o-block
        int kb = tid & 31;
        float s = __ldg(&wsi[((n_cta >> 7) + ob) * K_ITERS + kb]);
        asm volatile("st.shared.f32 [%0], %1;" :: "r"(SCALE_SM + tid * 4), "f"(s));
    }
    __syncthreads();

    if (wid == 8) {
        // -------- producer (lane 0 of warp 8) --------
        if (lane == 0) {
#pragma unroll 1
            for (int i = 0; i < K_ITERS; ++i) {
                int s = i & (STAGES - 1);
                if (i >= STAGES) MBAR_WAIT(BAR_EMPTY(s), ((i >> 2) - 1) & 1);
                MBAR_EXPECT_TX(BAR_FULL(s), (uint32_t)(A_STG_B + B_STG_B));
                int k0 = i * KCHUNK;
                TMA_LOAD_3D(A_STAGE(s),           &tma_a, k0, m_cta,       0, BAR_FULL(s));
                TMA_LOAD_3D(B_STAGE(s),           &tma_b, k0, n_cta,       0, BAR_FULL(s));
                TMA_LOAD_3D(B_STAGE(s) + 128*128, &tma_b, k0, n_cta + 128, 0, BAR_FULL(s));
            }
        }
    } else {
        // -------- 8 consumer warps: warp tile 64(M) x 64(N) --------
        const int warp_m = wid & 1;          // 2 M sub-tiles of 64
        const int warp_n = wid >> 1;         // 4 N sub-tiles of 64
        const int m_off = warp_m * 64;
        const int n_off = warp_n * 64;
        const uint32_t sc_base = SCALE_SM + (n_off >> 7) * (K_ITERS * 4);

        // ldmatrix per-lane offsets within the fp8 tiles (pre-swizzle)
        const uint32_t a_off0 = (uint32_t)(m_off + (lane & 15)) * 128 + ((lane >> 4) << 4);
        const uint32_t b_off0 = (uint32_t)(n_off + (lane & 7) + ((lane >> 4) << 3)) * 128
                              + (((lane >> 3) & 1) << 4);

        float acc[4][8][4];                  // 4 m16 x 8 n8 fp32 accumulators
#pragma unroll
        for (int q = 0; q < 4; ++q)
#pragma unroll
            for (int g = 0; g < 8; ++g)
#pragma unroll
                for (int e = 0; e < 4; ++e) acc[q][g][e] = 0.f;

#pragma unroll 1
        for (int i = 0; i < K_ITERS; ++i) {
            int s = i & (STAGES - 1);
            MBAR_WAIT(BAR_FULL(s), (i >> 2) & 1);
            float sblk;
            asm volatile("ld.shared.f32 %0, [%1];" : "=f"(sblk) : "r"(sc_base + i * 4));
            __half2 sh2 = __float2half2_rn(sblk);
            uint32_t s2 = *reinterpret_cast<uint32_t*>(&sh2);
            uint32_t abase = A_STAGE(s);
            uint32_t bbase = B_STAGE(s);

#pragma unroll
            for (int ks = 0; ks < 4; ++ks) {
                // B: 64 rows of fp8 (k32 chunk) -> 8 n8-groups, even/odd k fragments
                uint32_t Bev[8][2], Bod[8][2];
#pragma unroll
                for (int p = 0; p < 4; ++p) {
                    uint32_t r0, r1, r2, r3;
                    LDSM_X4(r0, r1, r2, r3,
                            swz128(bbase, b_off0 + p * (16 * 128) + ks * 32));
                    Bev[2*p][0] = hmul2u(cvt_lo(r0), s2);
                    Bod[2*p][0] = hmul2u(cvt_hi(r0), s2);
                    Bev[2*p][1] = hmul2u(cvt_lo(r1), s2);
                    Bod[2*p][1] = hmul2u(cvt_hi(r1), s2);
                    Bev[2*p+1][0] = hmul2u(cvt_lo(r2), s2);
                    Bod[2*p+1][0] = hmul2u(cvt_hi(r2), s2);
                    Bev[2*p+1][1] = hmul2u(cvt_lo(r3), s2);
                    Bod[2*p+1][1] = hmul2u(cvt_hi(r3), s2);
                }
#pragma unroll
                for (int mt = 0; mt < 4; ++mt) {
                    uint32_t a0, a1, a2, a3;
                    LDSM_X4(a0, a1, a2, a3,
                            swz128(abase, a_off0 + mt * (16 * 128) + ks * 32));
                    uint32_t Aev[4] = { cvt_lo(a0), cvt_lo(a1), cvt_lo(a2), cvt_lo(a3) };
                    uint32_t Aod[4] = { cvt_hi(a0), cvt_hi(a1), cvt_hi(a2), cvt_hi(a3) };
#pragma unroll
                    for (int g = 0; g < 8; ++g) {
                        HMMA16816(acc[mt][g], Aev[0], Aev[1], Aev[2], Aev[3],
                                  Bev[g][0], Bev[g][1]);
                        HMMA16816(acc[mt][g], Aod[0], Aod[1], Aod[2], Aod[3],
                                  Bod[g][0], Bod[g][1]);
                    }
                }
            }
            if (lane == 0) MBAR_ARRIVE(BAR_EMPTY(s));
        }

        // -------- writeout: out[t, o] = acc * x_scale[t] --------
#pragma unroll
        for (int mt = 0; mt < 4; ++mt) {
            int r0 = m_cta + m_off + mt * 16 + (lane >> 2);
            int r1 = r0 + 8;
            float xs0 = g_xs[r0];
            float xs1 = g_xs[r1];
            float* p0 = out + (size_t)r0 * O_DIM + n_cta + n_off + (lane & 3) * 2;
            float* p1 = out + (size_t)r1 * O_DIM + n_cta + n_off + (lane & 3) * 2;
#pragma unroll
            for (int g = 0; g < 8; ++g) {
                float2 v0 = { acc[mt][g][0] * xs0, acc[mt][g][1] * xs0 };
                float2 v1 = { acc[mt][g][2] * xs1, acc[mt][g][3] * xs1 };
                *reinterpret_cast<float2*>(p0 + g * 8) = v0;
                *reinterpret_cast<float2*>(p1 + g * 8) = v1;
            }
        }
    }
}

// ===================== host =====================
typedef CUresult (*EncodeFn)(CUtensorMap*, CUtensorMapDataType, cuuint32_t, void*,
                             const cuuint64_t*, const cuuint64_t*, const cuuint32_t*,
                             const cuuint32_t*, CUtensorMapInterleave, CUtensorMapSwizzle,
                             CUtensorMapL2promotion, CUtensorMapFloatOOBfill);

static EncodeFn get_encode_fn() {
    void* fn = nullptr;
    cudaDriverEntryPointQueryResult qr;
#if CUDART_VERSION >= 12050
    cudaGetDriverEntryPointByVersion("cuTensorMapEncodeTiled", &fn, 12000,
                                     cudaEnableDefault, &qr);
#else
    cudaGetDriverEntryPoint("cuTensorMapEncodeTiled", &fn, cudaEnableDefault, &qr);
#endif
    return (EncodeFn)fn;
}

static void make_map_u8(EncodeFn enc, CUtensorMap* m, void* base, uint64_t d0, uint64_t d1) {
    cuuint64_t dims[3]    = {d0, d1, 1};
    cuuint64_t strides[2] = {d0, d0 * d1};
    cuuint32_t box[3]     = {128, 128, 1};       // 128 B = SW128 atom width
    cuuint32_t es[3]      = {1, 1, 1};
    enc(m, CU_TENSOR_MAP_DATA_TYPE_UINT8, 3, base, dims, strides, box, es,
        CU_TENSOR_MAP_INTERLEAVE_NONE, CU_TENSOR_MAP_SWIZZLE_128B,
        CU_TENSOR_MAP_L2_PROMOTION_L2_128B, CU_TENSOR_MAP_FLOAT_OOB_FILL_NONE);
}

extern "C" void kernel_launch(void* const* d_in, const int* in_sizes, int n_in,
                              void* d_out, int out_size) {
    const float* x   = (const float*)d_in[0];
    const float* w   = (const float*)d_in[1];
    const float* wsi = (const float*)d_in[2];
    float* out = (float*)d_out;

    void* xq_ptr = nullptr;
    void* wq_ptr = nullptr;
    cudaGetSymbolAddress(&xq_ptr, g_xq);
    cudaGetSymbolAddress(&wq_ptr, g_wq);

    EncodeFn enc = get_encode_fn();
    CUtensorMap tma_a, tma_b;
    make_map_u8(enc, &tma_a, xq_ptr, K_DIM, T_TOK);
    make_map_u8(enc, &tma_b, wq_ptr, K_DIM, O_DIM);

    quant_x_kernel<<<T_TOK, 256>>>(x);
    quant_w_kernel<<<(O_DIM * K_DIM) / (4 * 256), 256>>>(w);

    cudaFuncSetAttribute(gemm_kernel, cudaFuncAttributeMaxDynamicSharedMemorySize, SMEM_BYTES);
    gemm_kernel<<<(T_TOK / CTA_M) * (O_DIM / CTA_N), 288, SMEM_BYTES>>>(tma_a, tma_b, wsi, out);
}

// round 6
// speedup vs baseline: 1.1641x; 1.1641x over previous
#include <cuda_runtime.h>
#include <cuda.h>
#include <cuda_fp16.h>
#include <cstdint>

// ===================== problem dims =====================
static constexpr int T_TOK = 8192;   // tokens (M)
static constexpr int K_DIM = 4096;   // input size (K)
static constexpr int O_DIM = 6144;   // output size (N)
static constexpr float FP8_MAX = 448.0f;

// ===================== scratch (device globals; no allocation allowed) =====================
__device__ __align__(1024) __half g_xq[(size_t)T_TOK * K_DIM];   // 64 MB: fp16(e4m3(x/xs))
__device__ __align__(1024) __half g_wq[(size_t)O_DIM * K_DIM];   // 48 MB: fp16(e4m3(w)*scale)
__device__ float g_xs[T_TOK];

// ===================== PTX helpers =====================
__device__ __forceinline__ uint32_t smem_u32(const void* p) {
    uint32_t a;
    asm("{ .reg .u64 t; cvta.to.shared.u64 t, %1; cvt.u32.u64 %0, t; }" : "=r"(a) : "l"(p));
    return a;
}

#define MBAR_INIT(addr, cnt) \
    asm volatile("mbarrier.init.shared.b64 [%0], %1;" :: "r"(addr), "r"(cnt) : "memory")
#define MBAR_EXPECT_TX(addr, bytes) \
    asm volatile("mbarrier.arrive.expect_tx.shared.b64 _, [%0], %1;" :: "r"(addr), "r"(bytes) : "memory")
#define MBAR_ARRIVE(addr) \
    asm volatile("mbarrier.arrive.shared.b64 _, [%0];" :: "r"(addr) : "memory")

#define MBAR_WAIT(addr, ph) do {                                                   \
    asm volatile("{\n\t.reg .pred P;\n\tWL%=:\n\t"                                 \
        "mbarrier.try_wait.parity.acquire.cta.shared::cta.b64 P, [%0], %1, 0x989680;\n\t" \
        "@P bra.uni WD%=;\n\tbra.uni WL%=;\n\tWD%=:\n\t}"                          \
        :: "r"(addr), "r"(ph) : "memory");                                         \
} while (0)

#define TMA_LOAD_3D(dst, map, cx, cy, cz, mbar) \
    asm volatile("cp.async.bulk.tensor.3d.shared::cta.global.tile.mbarrier::complete_tx::bytes " \
                 "[%0], [%1, {%2, %3, %4}], [%5];" \
                 :: "r"((uint32_t)(dst)), "l"(map), "r"((int32_t)(cx)), "r"((int32_t)(cy)), \
                    "r"((int32_t)(cz)), "r"((uint32_t)(mbar)) : "memory")

#define LDSM_X4(r0, r1, r2, r3, addr) \
    asm volatile("ldmatrix.sync.aligned.m8n8.x4.shared.b16 {%0,%1,%2,%3}, [%4];" \
                 : "=r"(r0), "=r"(r1), "=r"(r2), "=r"(r3) : "r"(addr))

#define HMMA16816(c, a, b0v, b1v) \
    asm volatile("mma.sync.aligned.m16n8k16.row.col.f32.f16.f16.f32 " \
                 "{%0,%1,%2,%3},{%4,%5,%6,%7},{%8,%9},{%0,%1,%2,%3};" \
                 : "+f"((c)[0]), "+f"((c)[1]), "+f"((c)[2]), "+f"((c)[3]) \
                 : "r"((a)[0]), "r"((a)[1]), "r"((a)[2]), "r"((a)[3]), "r"(b0v), "r"(b1v))

__device__ __forceinline__ uint32_t swz128(uint32_t base, uint32_t off) {
    return base + (off ^ ((off >> 3) & 0x70));
}

// f32 pair -> e4m3x2 (RN satfinite) -> f16x2 (exact). lo -> low half.
__device__ __forceinline__ uint32_t f32x2_to_f16x2_via_e4m3(float lo, float hi) {
    unsigned short p; uint32_t r;
    asm volatile("cvt.rn.satfinite.e4m3x2.f32 %0, %1, %2;" : "=h"(p) : "f"(hi), "f"(lo));
    asm volatile("cvt.rn.f16x2.e4m3x2 %0, %1;" : "=r"(r) : "h"(p));
    return r;
}

// ===================== kernel 1: per-token quantize x -> f16(e4m3(x/xs)) =====================
__global__ void __launch_bounds__(256) quant_x_kernel(const float* __restrict__ x) {
    int row = blockIdx.x;
    int t = threadIdx.x;
    const float4* xr = reinterpret_cast<const float4*>(x + (size_t)row * K_DIM);
    float4 v[4];
    float amax = 0.f;
#pragma unroll
    for (int j = 0; j < 4; ++j) {
        v[j] = xr[t + 256 * j];
        amax = fmaxf(amax, fabsf(v[j].x));
        amax = fmaxf(amax, fabsf(v[j].y));
        amax = fmaxf(amax, fabsf(v[j].z));
        amax = fmaxf(amax, fabsf(v[j].w));
    }
#pragma unroll
    for (int off = 16; off > 0; off >>= 1)
        amax = fmaxf(amax, __shfl_xor_sync(0xFFFFFFFFu, amax, off));
    __shared__ float smax[8];
    if ((t & 31) == 0) smax[t >> 5] = amax;
    __syncthreads();
    float rmax = smax[0];
#pragma unroll
    for (int j = 1; j < 8; ++j) rmax = fmaxf(rmax, smax[j]);
    float scale = fmaxf(rmax, 1e-12f) / FP8_MAX;
    if (t == 0) g_xs[row] = scale;
    float inv = 1.0f / scale;          // one exact div per row; FMUL below (e4m3 absorbs ulp noise)
    uint2* outr = reinterpret_cast<uint2*>(g_xq + (size_t)row * K_DIM);
#pragma unroll
    for (int j = 0; j < 4; ++j) {
        uint2 o;
        o.x = f32x2_to_f16x2_via_e4m3(v[j].x * inv, v[j].y * inv);
        o.y = f32x2_to_f16x2_via_e4m3(v[j].z * inv, v[j].w * inv);
        outr[t + 256 * j] = o;
    }
}

// ===================== kernel 2: dequantize weights -> f16(e4m3(w)*scale) =====================
__global__ void __launch_bounds__(256) dequant_w_kernel(const float* __restrict__ w,
                                                        const float* __restrict__ wsi) {
    int idx4 = blockIdx.x * 256 + threadIdx.x;   // float4 index
    int i4 = idx4 << 2;
    int o = i4 >> 12;            // / 4096
    int i = i4 & (K_DIM - 1);
    float scale = wsi[(o >> 7) * (K_DIM / 128) + (i >> 7)];
    float4 v = reinterpret_cast<const float4*>(w)[idx4];
    uint32_t h01 = f32x2_to_f16x2_via_e4m3(v.x, v.y);   // e4m3 values, exact in f16
    uint32_t h23 = f32x2_to_f16x2_via_e4m3(v.z, v.w);
    __half2 a = *reinterpret_cast<__half2*>(&h01);
    __half2 b = *reinterpret_cast<__half2*>(&h23);
    float2 fa = __half22float2(a), fb = __half22float2(b);
    __half2 ra = __floats2half2_rn(fa.x * scale, fa.y * scale);  // f32 product, f16 RN
    __half2 rb = __floats2half2_rn(fb.x * scale, fb.y * scale);
    uint2 oo;
    oo.x = *reinterpret_cast<uint32_t*>(&ra);
    oo.y = *reinterpret_cast<uint32_t*>(&rb);
    reinterpret_cast<uint2*>(g_wq)[idx4] = oo;
}

// ===================== kernel 3: fp16 HMMA GEMM, TMA pipeline, no clusters =====================
static constexpr int STAGES   = 4;
static constexpr int KCHUNK   = 64;                 // fp16 elems per stage (=128B row)
static constexpr int K_ITERS  = K_DIM / KCHUNK;     // 64
static constexpr int TILE_N   = 512;                // per-CTA N band (2 passes of 256)
static constexpr int NHALF    = 256;
static constexpr int A_STG_B  = 128 * 128;          // 16 KB
static constexpr int B_STG_B  = 2 * 128 * 128;      // 32 KB
static constexpr int OFF_A    = 1024;
static constexpr int OFF_B    = OFF_A + STAGES * A_STG_B;
static constexpr int SMEM_BYTES = OFF_B + STAGES * B_STG_B;  // 197632

#define BAR_FULL(s)  (smem_base + 0  + (s) * 8)
#define BAR_EMPTY(s) (smem_base + 64 + (s) * 8)
#define A_STAGE(s)   (smem_base + OFF_A + (s) * A_STG_B)
#define B_STAGE(s,h) (smem_base + OFF_B + (s) * B_STG_B + (h) * (128 * 128))

__global__ void __launch_bounds__(288, 1)
gemm_kernel(const __grid_constant__ CUtensorMap tma_a,
            const __grid_constant__ CUtensorMap tma_b,
            float* __restrict__ out) {
    extern __shared__ char smem[];
    const uint32_t smem_base = smem_u32(smem);
    const int tid = threadIdx.x;
    const int wid = tid >> 5;
    const int lane = tid & 31;

    const int m_cta  = (blockIdx.x & 63) * 128;     // m fastest: concurrent CTAs share B in L2
    const int n_base = (blockIdx.x >> 6) * TILE_N;  // 12 N bands

    if (tid == 0) {
        for (int s = 0; s < STAGES; ++s) {
            MBAR_INIT(BAR_FULL(s), 1);
            MBAR_INIT(BAR_EMPTY(s), 8);   // 8 consumer warps
        }
    }
    __syncthreads();

    if (wid == 8) {
        // -------- producer (lane 0 of warp 8) --------
        if (lane == 0) {
#pragma unroll 1
            for (int it = 0; it < 2 * K_ITERS; ++it) {
                int s = it & (STAGES - 1);
                if (it >= STAGES) MBAR_WAIT(BAR_EMPTY(s), ((it >> 2) - 1) & 1);
                MBAR_EXPECT_TX(BAR_FULL(s), (uint32_t)(A_STG_B + B_STG_B));
                int h = it >> 6;            // N half (0/1)
                int k0 = (it & 63) * KCHUNK;
                int nb = n_base + h * NHALF;
                TMA_LOAD_3D(A_STAGE(s),    &tma_a, k0, m_cta,    0, BAR_FULL(s));
                TMA_LOAD_3D(B_STAGE(s, 0), &tma_b, k0, nb,       0, BAR_FULL(s));
                TMA_LOAD_3D(B_STAGE(s, 1), &tma_b, k0, nb + 128, 0, BAR_FULL(s));
            }
        }
    } else {
        // -------- 8 consumer warps: warp tile 64(M) x 64(N) --------
        const int warp_m = wid & 1;          // 2 M sub-tiles of 64
        const int warp_n = wid >> 1;         // 4 N sub-tiles of 64
        const int m_off = warp_m * 64;
        const int bsub  = warp_n >> 1;                 // which 128-row B subtile
        const int brow  = (warp_n & 1) * 64;           // row offset within subtile

        const uint32_t lrow = lane & 15;
        const uint32_t lkb  = (lane >> 4) * 16;
        const uint32_t a_off0 = (m_off + lrow) * 128 + lkb;
        const uint32_t b_off0 = (brow  + lrow) * 128 + lkb;

        float acc[4][8][4];
#pragma unroll
        for (int mt = 0; mt < 4; ++mt)
#pragma unroll
            for (int nt = 0; nt < 8; ++nt)
#pragma unroll
                for (int e = 0; e < 4; ++e) acc[mt][nt][e] = 0.f;

#pragma unroll 1
        for (int h = 0; h < 2; ++h) {
#pragma unroll 1
            for (int i = 0; i < K_ITERS; ++i) {
                int it = h * K_ITERS + i;
                int s = it & (STAGES - 1);
                MBAR_WAIT(BAR_FULL(s), (it >> 2) & 1);
                uint32_t abase = A_STAGE(s);
                uint32_t bbase = B_STAGE(s, bsub);
#pragma unroll
                for (int ks = 0; ks < 4; ++ks) {
                    uint32_t A[4][4], B[4][4];
#pragma unroll
                    for (int mt = 0; mt < 4; ++mt)
                        LDSM_X4(A[mt][0], A[mt][1], A[mt][2], A[mt][3],
                                swz128(abase, a_off0 + mt * (16 * 128) + ks * 32));
#pragma unroll
                    for (int ng = 0; ng < 4; ++ng)
                        LDSM_X4(B[ng][0], B[ng][1], B[ng][2], B[ng][3],
                                swz128(bbase, b_off0 + ng * (16 * 128) + ks * 32));
#pragma unroll
                    for (int mt = 0; mt < 4; ++mt)
#pragma unroll
                        for (int ng = 0; ng < 4; ++ng) {
                            HMMA16816(acc[mt][2 * ng],     A[mt], B[ng][0], B[ng][2]);
                            HMMA16816(acc[mt][2 * ng + 1], A[mt], B[ng][1], B[ng][3]);
                        }
                }
                if (lane == 0) MBAR_ARRIVE(BAR_EMPTY(s));
            }

            // -------- writeout for this N half, then clear acc --------
            const int n_w = n_base + h * NHALF + warp_n * 64 + (lane & 3) * 2;
#pragma unroll
            for (int mt = 0; mt < 4; ++mt) {
                int r0 = m_cta + m_off + mt * 16 + (lane >> 2);
                int r1 = r0 + 8;
                float xs0 = g_xs[r0];
                float xs1 = g_xs[r1];
                float* p0 = out + (size_t)r0 * O_DIM + n_w;
                float* p1 = out + (size_t)r1 * O_DIM + n_w;
#pragma unroll
                for (int nt = 0; nt < 8; ++nt) {
                    float2 v0 = { acc[mt][nt][0] * xs0, acc[mt][nt][1] * xs0 };
                    float2 v1 = { acc[mt][nt][2] * xs1, acc[mt][nt][3] * xs1 };
                    *reinterpret_cast<float2*>(p0 + nt * 8) = v0;
                    *reinterpret_cast<float2*>(p1 + nt * 8) = v1;
#pragma unroll
                    for (int e = 0; e < 4; ++e) acc[mt][nt][e] = 0.f;
                }
            }
        }
    }
}

// ===================== host =====================
typedef CUresult (*EncodeFn)(CUtensorMap*, CUtensorMapDataType, cuuint32_t, void*,
                             const cuuint64_t*, const cuuint64_t*, const cuuint32_t*,
                             const cuuint32_t*, CUtensorMapInterleave, CUtensorMapSwizzle,
                             CUtensorMapL2promotion, CUtensorMapFloatOOBfill);

static EncodeFn get_encode_fn() {
    void* fn = nullptr;
    cudaDriverEntryPointQueryResult qr;
#if CUDART_VERSION >= 12050
    cudaGetDriverEntryPointByVersion("cuTensorMapEncodeTiled", &fn, 12000,
                                     cudaEnableDefault, &qr);
#else
    cudaGetDriverEntryPoint("cuTensorMapEncodeTiled", &fn, cudaEnableDefault, &qr);
#endif
    return (EncodeFn)fn;
}

static void make_map_f16(EncodeFn enc, CUtensorMap* m, void* base, uint64_t d0, uint64_t d1) {
    cuuint64_t dims[3]    = {d0, d1, 1};
    cuuint64_t strides[2] = {d0 * 2, d0 * d1 * 2};
    cuuint32_t box[3]     = {64, 128, 1};        // 64 fp16 = 128B = SW128 atom
    cuuint32_t es[3]      = {1, 1, 1};
    enc(m, CU_TENSOR_MAP_DATA_TYPE_FLOAT16, 3, base, dims, strides, box, es,
        CU_TENSOR_MAP_INTERLEAVE_NONE, CU_TENSOR_MAP_SWIZZLE_128B,
        CU_TENSOR_MAP_L2_PROMOTION_L2_128B, CU_TENSOR_MAP_FLOAT_OOB_FILL_NONE);
}

extern "C" void kernel_launch(void* const* d_in, const int* in_sizes, int n_in,
                              void* d_out, int out_size) {
    const float* x   = (const float*)d_in[0];
    const float* w   = (const float*)d_in[1];
    const float* wsi = (const float*)d_in[2];
    float* out = (float*)d_out;

    void* xq_ptr = nullptr;
    void* wq_ptr = nullptr;
    cudaGetSymbolAddress(&xq_ptr, g_xq);
    cudaGetSymbolAddress(&wq_ptr, g_wq);

    EncodeFn enc = get_encode_fn();
    CUtensorMap tma_a, tma_b;
    make_map_f16(enc, &tma_a, xq_ptr, K_DIM, T_TOK);
    make_map_f16(enc, &tma_b, wq_ptr, K_DIM, O_DIM);

    quant_x_kernel<<<T_TOK, 256>>>(x);
    dequant_w_kernel<<<(O_DIM * K_DIM) / (4 * 256), 256>>>(w, wsi);

    cudaFuncSetAttribute(gemm_kernel, cudaFuncAttributeMaxDynamicSharedMemorySize, SMEM_BYTES);
    gemm_kernel<<<(T_TOK / 128) * (O_DIM / TILE_N), 288, SMEM_BYTES>>>(tma_a, tma_b, out);
}

// round 7
// speedup vs baseline: 4.2542x; 3.6545x over previous
#include <cuda_runtime.h>
#include <cuda.h>
#include <cuda_fp16.h>
#include <cstdint>

// Feature gate: tcgen05 exists only in the arch-specific sm_103a/sm_100a cubin pass.
// The harness ALSO builds a compute_103 PTX pass (where this is undefined) — that pass
// gets the mma.sync fallback below so compilation succeeds; at runtime the driver
// prefers the sm_103a cubin, which runs the tcgen05 path (proven by R3 vs R6 timing).
#if defined(__CUDA_ARCH__) && (defined(__CUDA_ARCH_FEAT_SM103_ALL) || defined(__CUDA_ARCH_FEAT_SM100_ALL))
#define HAS_TCGEN05 1
#else
#define HAS_TCGEN05 0
#endif

// ===================== problem dims =====================
static constexpr int T_TOK = 8192;   // tokens (M)
static constexpr int K_DIM = 4096;   // input size (K)
static constexpr int O_DIM = 6144;   // output size (N)
static constexpr float FP8_MAX = 448.0f;

// ===================== scratch (device globals; no allocation allowed) =====================
__device__ __align__(1024) __half g_xq[(size_t)T_TOK * K_DIM];   // 64 MB: fp16(e4m3(x/xs))
__device__ __align__(1024) __half g_wq[(size_t)O_DIM * K_DIM];   // 48 MB: fp16(e4m3(w)*scale)
__device__ float g_xs[T_TOK];

// ===================== small PTX helpers =====================
__device__ __forceinline__ uint32_t smem_u32(const void* p) {
    uint32_t a;
    asm("{ .reg .u64 t; cvta.to.shared.u64 t, %1; cvt.u32.u64 %0, t; }" : "=r"(a) : "l"(p));
    return a;
}
__device__ __forceinline__ uint32_t ctarank() {
    uint32_t r; asm("mov.u32 %0, %%cluster_ctarank;" : "=r"(r)); return r;
}

#define MBAR_INIT(addr, cnt) \
    asm volatile("mbarrier.init.shared.b64 [%0], %1;" :: "r"(addr), "r"(cnt) : "memory")
#define MBAR_EXPECT_TX(addr, bytes) \
    asm volatile("mbarrier.arrive.expect_tx.shared.b64 _, [%0], %1;" :: "r"(addr), "r"(bytes) : "memory")
#define MBAR_ARRIVE(addr) \
    asm volatile("mbarrier.arrive.shared.b64 _, [%0];" :: "r"(addr) : "memory")
#define MBAR_ARRIVE_CLUSTER(addr, rnk) \
    asm volatile("{\n\t.reg .b32 ra;\n\tmapa.shared::cluster.u32 ra, %0, %1;\n\t" \
                 "mbarrier.arrive.release.cluster.shared::cluster.b64 _, [ra];\n\t}" \
                 :: "r"(addr), "r"(rnk) : "memory")

#define MBAR_WAIT(addr, ph) do {                                                   \
    asm volatile("{\n\t.reg .pred P;\n\tWL%=:\n\t"                                 \
        "mbarrier.try_wait.parity.acquire.cta.shared::cta.b64 P, [%0], %1, 0x989680;\n\t" \
        "@P bra.uni WD%=;\n\tbra.uni WL%=;\n\tWD%=:\n\t}"                          \
        :: "r"(addr), "r"(ph) : "memory");                                         \
} while (0)

#define MBAR_WAIT_CLUSTER(addr, ph) do {                                           \
    asm volatile("{\n\t.reg .pred P;\n\tWL%=:\n\t"                                 \
        "mbarrier.try_wait.parity.acquire.cluster.shared::cta.b64 P, [%0], %1, 0x989680;\n\t" \
        "@P bra.uni WD%=;\n\tbra.uni WL%=;\n\tWD%=:\n\t}"                          \
        :: "r"(addr), "r"(ph) : "memory");                                         \
} while (0)

#define TMA_LOAD_3D(dst, map, cx, cy, cz, mbar) \
    asm volatile("cp.async.bulk.tensor.3d.shared::cta.global.tile.mbarrier::complete_tx::bytes " \
                 "[%0], [%1, {%2, %3, %4}], [%5];" \
                 :: "r"((uint32_t)(dst)), "l"(map), "r"((int32_t)(cx)), "r"((int32_t)(cy)), \
                    "r"((int32_t)(cz)), "r"((uint32_t)(mbar)) : "memory")

#define CLUSTER_SYNC() do { \
    asm volatile("barrier.cluster.arrive.aligned;" ::: "memory"); \
    asm volatile("barrier.cluster.wait.aligned;"   ::: "memory"); \
} while (0)

// f32 pair -> e4m3x2 (RN satfinite) -> f16x2 (exact). lo -> low half.
__device__ __forceinline__ uint32_t f32x2_to_f16x2_via_e4m3(float lo, float hi) {
    unsigned short p; uint32_t r;
    asm volatile("cvt.rn.satfinite.e4m3x2.f32 %0, %1, %2;" : "=h"(p) : "f"(hi), "f"(lo));
    asm volatile("cvt.rn.f16x2.e4m3x2 %0, %1;" : "=r"(r) : "h"(p));
    return r;
}

// ===================== fused prep: quant_x (blocks 0..8191) + dequant_w (rest) =====================
__global__ void __launch_bounds__(256) prep_kernel(const float* __restrict__ x,
                                                   const float* __restrict__ w,
                                                   const float* __restrict__ wsi) {
    __shared__ float smax[8];
    int t = threadIdx.x;
    if (blockIdx.x < T_TOK) {
        // ---- per-token quantize x ----
        int row = blockIdx.x;
        const float4* xr = reinterpret_cast<const float4*>(x + (size_t)row * K_DIM);
        float4 v[4];
        float amax = 0.f;
#pragma unroll
        for (int j = 0; j < 4; ++j) {
            v[j] = xr[t + 256 * j];
            amax = fmaxf(amax, fabsf(v[j].x));
            amax = fmaxf(amax, fabsf(v[j].y));
            amax = fmaxf(amax, fabsf(v[j].z));
            amax = fmaxf(amax, fabsf(v[j].w));
        }
#pragma unroll
        for (int off = 16; off > 0; off >>= 1)
            amax = fmaxf(amax, __shfl_xor_sync(0xFFFFFFFFu, amax, off));
        if ((t & 31) == 0) smax[t >> 5] = amax;
        __syncthreads();
        float rmax = smax[0];
#pragma unroll
        for (int j = 1; j < 8; ++j) rmax = fmaxf(rmax, smax[j]);
        float scale = fmaxf(rmax, 1e-12f) / FP8_MAX;
        if (t == 0) g_xs[row] = scale;
        float inv = 1.0f / scale;   // e4m3 RN absorbs the +-1ulp vs exact division
        uint2* outr = reinterpret_cast<uint2*>(g_xq + (size_t)row * K_DIM);
#pragma unroll
        for (int j = 0; j < 4; ++j) {
            uint2 o;
            o.x = f32x2_to_f16x2_via_e4m3(v[j].x * inv, v[j].y * inv);
            o.y = f32x2_to_f16x2_via_e4m3(v[j].z * inv, v[j].w * inv);
            outr[t + 256 * j] = o;
        }
    } else {
        // ---- dequantize w -> f16(e4m3(w) * scale) ----
        int b = blockIdx.x - T_TOK;
#pragma unroll
        for (int j = 0; j < 4; ++j) {
            int idx4 = b * 1024 + t + 256 * j;   // float4 index
            int i4 = idx4 << 2;
            int o = i4 >> 12;            // / 4096
            int i = i4 & (K_DIM - 1);
            float scale = wsi[(o >> 7) * (K_DIM / 128) + (i >> 7)];
            float4 v = reinterpret_cast<const float4*>(w)[idx4];
            uint32_t h01 = f32x2_to_f16x2_via_e4m3(v.x, v.y);
            uint32_t h23 = f32x2_to_f16x2_via_e4m3(v.z, v.w);
            __half2 a = *reinterpret_cast<__half2*>(&h01);
            __half2 bb = *reinterpret_cast<__half2*>(&h23);
            float2 fa = __half22float2(a), fb = __half22float2(bb);
            __half2 ra = __floats2half2_rn(fa.x * scale, fa.y * scale);
            __half2 rb = __floats2half2_rn(fb.x * scale, fb.y * scale);
            uint2 oo;
            oo.x = *reinterpret_cast<uint32_t*>(&ra);
            oo.y = *reinterpret_cast<uint32_t*>(&rb);
            reinterpret_cast<uint2*>(g_wq)[idx4] = oo;
        }
    }
}

// ===================== GEMM tiling =====================
static constexpr int STAGES   = 4;
static constexpr int KCHUNK   = 64;                 // fp16 elems per stage (=128B row)
static constexpr int K_ITERS  = K_DIM / KCHUNK;     // 64
static constexpr int TILE_N   = 512;                // per pair (tcgen05) / per CTA (fallback)
static constexpr int NHALF    = 256;
static constexpr int A_STG_B  = 128 * 128;          // 16 KB
static constexpr int B_STG_B  = 2 * 128 * 128;      // 32 KB
static constexpr int OFF_A    = 1024;
static constexpr int OFF_B    = OFF_A + STAGES * A_STG_B;
static constexpr int SMEM_BYTES = OFF_B + STAGES * B_STG_B;  // 197632

#define BAR_FULL(s)  (smem_base + 0   + (s) * 8)
#define BAR_EMPTY(s) (smem_base + 32  + (s) * 8)
#define BAR_FWD(s)   (smem_base + 64  + (s) * 8)
#define BAR_DONE     (smem_base + 96)
#define TMEM_PTR     (smem_base + 112)
#define A_STAGE(s)   (smem_base + OFF_A + (s) * A_STG_B)
#define B_STAGE(s,h) (smem_base + OFF_B + (s) * B_STG_B + (h) * (128 * 128))

#if HAS_TCGEN05
// ----- tcgen05-only helpers -----
#define TCGEN05_ALLOC_CG2(smem_addr, ncols) \
    asm volatile("tcgen05.alloc.cta_group::2.sync.aligned.shared::cta.b32 [%0], %1;" \
                 :: "r"((uint32_t)(smem_addr)), "r"((uint32_t)(ncols)) : "memory")
#define TCGEN05_DEALLOC_CG2(tmem, ncols) \
    asm volatile("tcgen05.dealloc.cta_group::2.sync.aligned.b32 %0, %1;" :: "r"(tmem), "r"(ncols))
#define TCGEN05_RELINQ_CG2() \
    asm volatile("tcgen05.relinquish_alloc_permit.cta_group::2.sync.aligned;")
#define TCGEN05_COMMIT_MC_CG2(mbar, mask) \
    asm volatile("tcgen05.commit.cta_group::2.mbarrier::arrive::one.shared::cluster.multicast::cluster.b64 [%0], %1;" \
                 :: "r"((uint32_t)(mbar)), "h"((uint16_t)(mask)) : "memory")
#define TCGEN05_FENCE_AFTER()  asm volatile("tcgen05.fence::after_thread_sync;" ::: "memory")
#define TCGEN05_WAIT_LD()      asm volatile("tcgen05.wait::ld.sync.aligned;" ::: "memory")
#define TCGEN05_LD_X32(r, addr) \
    asm volatile("tcgen05.ld.sync.aligned.32x32b.x32.b32 " \
        "{%0, %1, %2, %3, %4, %5, %6, %7, %8, %9, %10, %11, %12, %13, %14, %15, " \
        " %16, %17, %18, %19, %20, %21, %22, %23, %24, %25, %26, %27, %28, %29, %30, %31}, [%32];" \
        : "=r"((r)[0]),  "=r"((r)[1]),  "=r"((r)[2]),  "=r"((r)[3]),  "=r"((r)[4]),  "=r"((r)[5]), \
          "=r"((r)[6]),  "=r"((r)[7]),  "=r"((r)[8]),  "=r"((r)[9]),  "=r"((r)[10]), "=r"((r)[11]), \
          "=r"((r)[12]), "=r"((r)[13]), "=r"((r)[14]), "=r"((r)[15]), "=r"((r)[16]), "=r"((r)[17]), \
          "=r"((r)[18]), "=r"((r)[19]), "=r"((r)[20]), "=r"((r)[21]), "=r"((r)[22]), "=r"((r)[23]), \
          "=r"((r)[24]), "=r"((r)[25]), "=r"((r)[26]), "=r"((r)[27]), "=r"((r)[28]), "=r"((r)[29]), \
          "=r"((r)[30]), "=r"((r)[31]) : "r"(addr))

static constexpr uint64_t SMEM_DESC_BASE_SW128 =
    (uint64_t(2) << 61) | (uint64_t(1) << 46) | (uint64_t(64) << 32) | (uint64_t(1) << 16);
__device__ __forceinline__ uint64_t make_desc(uint32_t addr) {
    return SMEM_DESC_BASE_SW128 | ((uint64_t)(addr >> 4) & 0x3FFF);
}
__device__ __forceinline__ void mma_f16_ss_cg2(uint32_t d, uint64_t a, uint64_t b,
                                               uint32_t idesc, bool acc) {
    uint32_t en = acc ? 1u : 0u;
    asm volatile(
        "{\n\t.reg .pred p;\n\tsetp.ne.u32 p, %5, 0;\n\t"
        "tcgen05.mma.cta_group::2.kind::f16 [%0], %1, %2, %3, "
        "{%4, %4, %4, %4, %4, %4, %4, %4}, p;\n\t}"
        :: "r"(d), "l"(a), "l"(b), "r"(idesc), "r"(0u), "r"(en) : "memory");
}
static constexpr uint32_t IDESC =
    (1u << 4) | ((NHALF / 8) << 17) | ((256 / 16) << 24);
#endif // HAS_TCGEN05

// ----- fallback-only helpers (baseline PTX, compiles on plain sm_103) -----
#define LDSM_X4(r0, r1, r2, r3, addr) \
    asm volatile("ldmatrix.sync.aligned.m8n8.x4.shared.b16 {%0,%1,%2,%3}, [%4];" \
                 : "=r"(r0), "=r"(r1), "=r"(r2), "=r"(r3) : "r"(addr))
#define HMMA16816(c, a, b0v, b1v) \
    asm volatile("mma.sync.aligned.m16n8k16.row.col.f32.f16.f16.f32 " \
                 "{%0,%1,%2,%3},{%4,%5,%6,%7},{%8,%9},{%0,%1,%2,%3};" \
                 : "+f"((c)[0]), "+f"((c)[1]), "+f"((c)[2]), "+f"((c)[3]) \
                 : "r"((a)[0]), "r"((a)[1]), "r"((a)[2]), "r"((a)[3]), "r"(b0v), "r"(b1v))

__device__ __forceinline__ uint32_t swz128(uint32_t base, uint32_t off) {
    return base + (off ^ ((off >> 3) & 0x70));
}

// ===================== kernel 3: GEMM (tcgen05 or mma.sync fallback) =====================
__global__ void __launch_bounds__(288, 1) __cluster_dims__(2, 1, 1)
gemm_kernel(const __grid_constant__ CUtensorMap tma_a,
            const __grid_constant__ CUtensorMap tma_b,
            float* __restrict__ out) {
    extern __shared__ char smem[];
    const uint32_t smem_base = smem_u32(smem);
    const int tid = threadIdx.x;
    const int wid = tid >> 5;
    const int lane = tid & 31;

#if HAS_TCGEN05
    // ====================== tcgen05 cg2 path ======================
    const uint32_t rank = ctarank();
    const int pair = blockIdx.x >> 1;
    const int m_base = (pair & 31) * 256;      // m fastest: concurrent CTAs share B in L2
    const int n_base = (pair >> 5) * TILE_N;

    if (tid == 0) {
        for (int s = 0; s < STAGES; ++s) {
            MBAR_INIT(BAR_FULL(s), 1);
            MBAR_INIT(BAR_EMPTY(s), 1);
            MBAR_INIT(BAR_FWD(s), 1);
        }
        MBAR_INIT(BAR_DONE, 1);
    }
    __syncthreads();
    if (wid == 5) TCGEN05_ALLOC_CG2(TMEM_PTR, 512);
    __syncthreads();
    uint32_t tmem_base;
    asm volatile("ld.shared.b32 %0, [%1];" : "=r"(tmem_base) : "r"(TMEM_PTR));
    CLUSTER_SYNC();

    if (tid == 128) {   // producer
        for (int i = 0; i < K_ITERS; ++i) {
            int s = i & (STAGES - 1);
            if (i >= STAGES) MBAR_WAIT_CLUSTER(BAR_EMPTY(s), ((i >> 2) - 1) & 1);
            MBAR_EXPECT_TX(BAR_FULL(s), (uint32_t)(A_STG_B + B_STG_B));
            int k0 = i * KCHUNK;
            TMA_LOAD_3D(A_STAGE(s),    &tma_a, k0, m_base + (int)rank * 128, 0, BAR_FULL(s));
            TMA_LOAD_3D(B_STAGE(s, 0), &tma_b, k0, n_base + (int)rank * 128, 0, BAR_FULL(s));
            TMA_LOAD_3D(B_STAGE(s, 1), &tma_b, k0, n_base + NHALF + (int)rank * 128, 0, BAR_FULL(s));
        }
    }
    if (rank == 1 && tid == 160) {   // forward fullness to rank0
        for (int i = 0; i < K_ITERS; ++i) {
            int s = i & (STAGES - 1);
            MBAR_WAIT(BAR_FULL(s), (i >> 2) & 1);
            MBAR_ARRIVE_CLUSTER(BAR_FWD(s), 0);
        }
    }
    if (rank == 0 && tid == 160) {   // MMA issue
        for (int i = 0; i < K_ITERS; ++i) {
            int s = i & (STAGES - 1);
            int p = (i >> 2) & 1;
            MBAR_WAIT(BAR_FULL(s), p);
            MBAR_WAIT_CLUSTER(BAR_FWD(s), p);
            uint64_t ad = make_desc(A_STAGE(s));
            uint64_t b0 = make_desc(B_STAGE(s, 0));
            uint64_t b1 = make_desc(B_STAGE(s, 1));
#pragma unroll
            for (int ks = 0; ks < 4; ++ks) {
                bool acc = (i > 0) || (ks > 0);
                mma_f16_ss_cg2(tmem_base,         ad + ks * 2, b0 + ks * 2, IDESC, acc);
                mma_f16_ss_cg2(tmem_base + NHALF, ad + ks * 2, b1 + ks * 2, IDESC, acc);
            }
            TCGEN05_COMMIT_MC_CG2(BAR_EMPTY(s), 0x3);
        }
        TCGEN05_COMMIT_MC_CG2(BAR_DONE, 0x3);
    }

    if (wid < 4) {   // epilogue: TMEM -> regs (scale) -> SMEM transpose -> coalesced STG
        const int row_base = m_base + (int)rank * 128 + wid * 32;
        const float xs = g_xs[row_base + lane];           // prefetch before wait
        MBAR_WAIT_CLUSTER(BAR_DONE, 0);
        TCGEN05_FENCE_AFTER();
        // per-warp staging buffer in the (now idle) A-stage area: 32 rows x 36 floats
        const uint32_t tb = smem_base + OFF_A + (uint32_t)wid * 4672;
#pragma unroll 1
        for (int cb = 0; cb < TILE_N / 32; ++cb) {
            uint32_t r[32];
            TCGEN05_LD_X32(r, tmem_base + cb * 32);
            TCGEN05_WAIT_LD();
#pragma unroll
            for (int c = 0; c < 32; c += 4) {
                float vx = __uint_as_float(r[c + 0]) * xs;
                float vy = __uint_as_float(r[c + 1]) * xs;
                float vz = __uint_as_float(r[c + 2]) * xs;
                float vw = __uint_as_float(r[c + 3]) * xs;
                asm volatile("st.shared.v4.f32 [%0], {%1, %2, %3, %4};"
                    :: "r"(tb + (uint32_t)(lane * 36 + c) * 4),
                       "f"(vx), "f"(vy), "f"(vz), "f"(vw) : "memory");
            }
            __syncwarp();
#pragma unroll
            for (int ps = 0; ps < 8; ++ps) {
                int rr = ps * 4 + (lane >> 3);
                int cc = (lane & 7) * 4;
                float vx, vy, vz, vw;
                asm volatile("ld.shared.v4.f32 {%0, %1, %2, %3}, [%4];"
                    : "=f"(vx), "=f"(vy), "=f"(vz), "=f"(vw)
                    : "r"(tb + (uint32_t)(rr * 36 + cc) * 4));
                float4 v = {vx, vy, vz, vw};
                *reinterpret_cast<float4*>(out + (size_t)(row_base + rr) * O_DIM
                                           + n_base + cb * 32 + cc) = v;
            }
            __syncwarp();
        }
    }
    __syncthreads();
    if (wid == 5) {
        TCGEN05_RELINQ_CG2();
        TCGEN05_DEALLOC_CG2(tmem_base, 512);
    }
    CLUSTER_SYNC();

#else
    // ====================== fallback: ldmatrix + mma.sync path ======================
    const int pair = blockIdx.x >> 1;
    const int rank = blockIdx.x & 1;
    const int m_cta = (pair & 31) * 256 + rank * 128;
    const int n_base = (pair >> 5) * TILE_N;

    if (tid == 0) {
        for (int s = 0; s < STAGES; ++s) {
            MBAR_INIT(BAR_FULL(s), 1);
            MBAR_INIT(BAR_EMPTY(s), 8);
        }
    }
    __syncthreads();

    if (wid == 8) {
        if (lane == 0) {
#pragma unroll 1
            for (int it = 0; it < 2 * K_ITERS; ++it) {
                int s = it & (STAGES - 1);
                if (it >= STAGES) MBAR_WAIT(BAR_EMPTY(s), ((it >> 2) - 1) & 1);
                MBAR_EXPECT_TX(BAR_FULL(s), (uint32_t)(A_STG_B + B_STG_B));
                int h = it >> 6;
                int k0 = (it & 63) * KCHUNK;
                int nb = n_base + h * NHALF;
                TMA_LOAD_3D(A_STAGE(s),    &tma_a, k0, m_cta,    0, BAR_FULL(s));
                TMA_LOAD_3D(B_STAGE(s, 0), &tma_b, k0, nb,       0, BAR_FULL(s));
                TMA_LOAD_3D(B_STAGE(s, 1), &tma_b, k0, nb + 128, 0, BAR_FULL(s));
            }
        }
    } else {
        const int warp_m = wid & 1;
        const int warp_n = wid >> 1;
        const int m_off = warp_m * 64;
        const int bsub  = warp_n >> 1;
        const int brow  = (warp_n & 1) * 64;

        const uint32_t lrow = lane & 15;
        const uint32_t lkb  = (lane >> 4) * 16;
        const uint32_t a_off0 = (m_off + lrow) * 128 + lkb;
        const uint32_t b_off0 = (brow  + lrow) * 128 + lkb;

        float acc[4][8][4];
#pragma unroll
        for (int mt = 0; mt < 4; ++mt)
#pragma unroll
            for (int nt = 0; nt < 8; ++nt)
#pragma unroll
                for (int e = 0; e < 4; ++e) acc[mt][nt][e] = 0.f;

#pragma unroll 1
        for (int h = 0; h < 2; ++h) {
#pragma unroll 1
            for (int i = 0; i < K_ITERS; ++i) {
                int it = h * K_ITERS + i;
                int s = it & (STAGES - 1);
                MBAR_WAIT(BAR_FULL(s), (it >> 2) & 1);
                uint32_t abase = A_STAGE(s);
                uint32_t bbase = B_STAGE(s, bsub);
#pragma unroll
                for (int ks = 0; ks < 4; ++ks) {
                    uint32_t A[4][4], B[4][4];
#pragma unroll
                    for (int mt = 0; mt < 4; ++mt)
                        LDSM_X4(A[mt][0], A[mt][1], A[mt][2], A[mt][3],
                                swz128(abase, a_off0 + mt * (16 * 128) + ks * 32));
#pragma unroll
                    for (int ng = 0; ng < 4; ++ng)
                        LDSM_X4(B[ng][0], B[ng][1], B[ng][2], B[ng][3],
                                swz128(bbase, b_off0 + ng * (16 * 128) + ks * 32));
#pragma unroll
                    for (int mt = 0; mt < 4; ++mt)
#pragma unroll
                        for (int ng = 0; ng < 4; ++ng) {
                            HMMA16816(acc[mt][2 * ng],     A[mt], B[ng][0], B[ng][2]);
                            HMMA16816(acc[mt][2 * ng + 1], A[mt], B[ng][1], B[ng][3]);
                        }
                }
                if (lane == 0) MBAR_ARRIVE(BAR_EMPTY(s));
            }

            const int n_w = n_base + h * NHALF + warp_n * 64 + (lane & 3) * 2;
#pragma unroll
            for (int mt = 0; mt < 4; ++mt) {
                int r0 = m_cta + m_off + mt * 16 + (lane >> 2);
                int r1 = r0 + 8;
                float xs0 = g_xs[r0];
                float xs1 = g_xs[r1];
                float* p0 = out + (size_t)r0 * O_DIM + n_w;
                float* p1 = out + (size_t)r1 * O_DIM + n_w;
#pragma unroll
                for (int nt = 0; nt < 8; ++nt) {
                    float2 v0 = { acc[mt][nt][0] * xs0, acc[mt][nt][1] * xs0 };
                    float2 v1 = { acc[mt][nt][2] * xs1, acc[mt][nt][3] * xs1 };
                    *reinterpret_cast<float2*>(p0 + nt * 8) = v0;
                    *reinterpret_cast<float2*>(p1 + nt * 8) = v1;
#pragma unroll
                    for (int e = 0; e < 4; ++e) acc[mt][nt][e] = 0.f;
                }
            }
        }
    }
#endif
}

// ===================== host =====================
typedef CUresult (*EncodeFn)(CUtensorMap*, CUtensorMapDataType, cuuint32_t, void*,
                             const cuuint64_t*, const cuuint64_t*, const cuuint32_t*,
                             const cuuint32_t*, CUtensorMapInterleave, CUtensorMapSwizzle,
                             CUtensorMapL2promotion, CUtensorMapFloatOOBfill);

static EncodeFn get_encode_fn() {
    void* fn = nullptr;
    cudaDriverEntryPointQueryResult qr;
#if CUDART_VERSION >= 12050
    cudaGetDriverEntryPointByVersion("cuTensorMapEncodeTiled", &fn, 12000,
                                     cudaEnableDefault, &qr);
#else
    cudaGetDriverEntryPoint("cuTensorMapEncodeTiled", &fn, cudaEnableDefault, &qr);
#endif
    return (EncodeFn)fn;
}

static void make_map_f16(EncodeFn enc, CUtensorMap* m, void* base, uint64_t d0, uint64_t d1) {
    cuuint64_t dims[3]    = {d0, d1, 1};
    cuuint64_t strides[2] = {d0 * 2, d0 * d1 * 2};
    cuuint32_t box[3]     = {64, 128, 1};        // 64 fp16 = 128B = SW128 atom
    cuuint32_t es[3]      = {1, 1, 1};
    enc(m, CU_TENSOR_MAP_DATA_TYPE_FLOAT16, 3, base, dims, strides, box, es,
        CU_TENSOR_MAP_INTERLEAVE_NONE, CU_TENSOR_MAP_SWIZZLE_128B,
        CU_TENSOR_MAP_L2_PROMOTION_L2_128B, CU_TENSOR_MAP_FLOAT_OOB_FILL_NONE);
}

extern "C" void kernel_launch(void* const* d_in, const int* in_sizes, int n_in,
                              void* d_out, int out_size) {
    const float* x   = (const float*)d_in[0];
    const float* w   = (const float*)d_in[1];
    const float* wsi = (const float*)d_in[2];
    float* out = (float*)d_out;

    void* xq_ptr = nullptr;
    void* wq_ptr = nullptr;
    cudaGetSymbolAddress(&xq_ptr, g_xq);
    cudaGetSymbolAddress(&wq_ptr, g_wq);

    EncodeFn enc = get_encode_fn();
    CUtensorMap tma_a, tma_b;
    make_map_f16(enc, &tma_a, xq_ptr, K_DIM, T_TOK);
    make_map_f16(enc, &tma_b, wq_ptr, K_DIM, O_DIM);

    // fused prep: 8192 quant_x blocks + 6144 dequant_w blocks (overlapping DRAM phases)
    prep_kernel<<<T_TOK + (O_DIM * K_DIM) / 4096, 256>>>(x, w, wsi);

    cudaFuncSetAttribute(gemm_kernel, cudaFuncAttributeMaxDynamicSharedMemorySize, SMEM_BYTES);
    gemm_kernel<<<(T_TOK / 256) * (O_DIM / TILE_N) * 2, 288, SMEM_BYTES>>>(tma_a, tma_b, out);
}